// round 12
// baseline (speedup 1.0000x reference)
#include <cuda_runtime.h>
#include <cuda_fp16.h>
#include <math.h>

#define BATCH   16
#define NPTS    256
#define FDIM    64
#define FPRIME  16
#define HDIM    128
#define TLUT    384            // knots uniform in u = d^2 over [0, 3]
#define UMAX    3.0f
#define ITILE   16
#define THREADS 512

// nearest-neighbor LUT in u = d^2: row t = 64 halves (128 B), g(sqrt(t*h_u))
__device__ __half g_lutHalf[TLUT * FDIM];

__device__ __forceinline__ float sp(float x) {
    return fmaxf(x, 0.0f) + log1pf(expf(-fabsf(x)));
}

// ---------------------------------------------------------------------------
// LUT build: 384 blocks x 128 threads; dot split into two 64-term half-sums.
// ---------------------------------------------------------------------------
__global__ __launch_bounds__(128)
void build_lut_kernel(const float* __restrict__ mp_w1,
                      const float* __restrict__ mp_b1,
                      const float* __restrict__ mp_w2,
                      const float* __restrict__ mp_b2) {
    __shared__ float hid[HDIM];
    __shared__ float part[2][FDIM];
    const int t = blockIdx.x, tid = threadIdx.x;
    const float u = (float)t * (UMAX / (float)TLUT);
    const float d = sqrtf(u);
    hid[tid] = sp(fmaf(d, mp_w1[tid], mp_b1[tid]));
    __syncthreads();
    {
        int ff = tid & 63, half = tid >> 6;
        float a = 0.0f;
        #pragma unroll 8
        for (int h = 0; h < 64; h++)
            a = fmaf(hid[half * 64 + h], __ldg(mp_w2 + (half * 64 + h) * FDIM + ff), a);
        part[half][ff] = a;
    }
    __syncthreads();
    if (tid < FDIM) {
        float a = mp_b2[tid] + part[0][tid] + part[1][tid];
        g_lutHalf[t * FDIM + tid] = __float2half_rn(sp(a));
    }
}

// ---------------------------------------------------------------------------
// Main fused kernel. CTA = (16-i tile, batch); grid 256; 512 thr; 2 CTAs/SM.
// SMEM (94208 B):
//   [0,    49152)  lutS  LUT rows (384 x 128 B)
//   [49152,81920)  fbS   f tile half2 [j*32 + lane]
//   [81920,90112)  tS    u16 pre-shifted byte-offset (it<<7), layout [j][i]
//   [90112,94208)  rS    float4 positions
// Overlays (after stage-1 sync):
//   partS @0     (16 i * 16 g * 32 lane u32 = 32768)       over lutS
//   fbarT @32768 (64 f * stride 18 f32 = 4608)             over lutS
//   h2S   @37376 (16 * 132 f32 = 8448; ends 45824)         over lutS
//   w1S   @49152 (64*128 f32 = 32768)                      over fbS
//   w2T   @81920 (16 p * stride 132 f32 = 8448)            over tS (+256B rS)
//   b1S   @90624, b2S @91136                               over rS tail
// ---------------------------------------------------------------------------
__global__ __launch_bounds__(THREADS, 2)
void property_predictor_main(const float* __restrict__ r,
                             const float* __restrict__ f,
                             const float* __restrict__ pc_w1,
                             const float* __restrict__ pc_b1,
                             const float* __restrict__ pc_w2,
                             const float* __restrict__ pc_b2,
                             float* __restrict__ out) {
    extern __shared__ char smem[];
    unsigned int*   fbS   = (unsigned int*)(smem + 49152);
    unsigned short* tS    = (unsigned short*)(smem + 81920);
    float4*         rS    = (float4*)(smem + 90112);
    unsigned int*   partS = (unsigned int*)smem;
    float* fbarT = (float*)(smem + 32768);
    float* h2S   = (float*)(smem + 37376);
    float* w1S   = (float*)(smem + 49152);
    float* w2T   = (float*)(smem + 81920);
    float* b1S   = (float*)(smem + 90624);
    float* b2S   = (float*)(smem + 91136);

    const int b    = blockIdx.y;
    const int i0   = blockIdx.x * ITILE;
    const int tid  = threadIdx.x;
    const int w    = tid >> 5;
    const int lane = tid & 31;

    // ---- tile loads (vectorized) ----
    {
        const uint4* lutG = (const uint4*)g_lutHalf;
        uint4* lutSv = (uint4*)smem;
        #pragma unroll
        for (int k = tid; k < TLUT * 8; k += THREADS) lutSv[k] = lutG[k];
    }
    {
        const float4* fbG = (const float4*)(f + (size_t)b * NPTS * FDIM);
        #pragma unroll
        for (int k = tid; k < NPTS * 16; k += THREADS) {
            float4 v = fbG[k];
            __half2 h0 = __floats2half2_rn(v.x, v.y);
            __half2 h1 = __floats2half2_rn(v.z, v.w);
            fbS[2 * k]     = *reinterpret_cast<unsigned int*>(&h0);
            fbS[2 * k + 1] = *reinterpret_cast<unsigned int*>(&h1);
        }
    }
    {
        const float* rG = r + (size_t)b * NPTS * 3;
        if (tid < NPTS)
            rS[tid] = make_float4(rG[3 * tid], rG[3 * tid + 1], rG[3 * tid + 2], 0.0f);
    }
    __syncthreads();

    // ---- stage A: nearest u-knot byte offsets, NO sqrt. tS[j*16 + i] ----
    {
        const float inv_h = (float)TLUT / UMAX;
        const int ii = tid & 15;               // fixed i per thread
        const int jb = tid >> 4;               // j-group: 8 j's, stride 32
        float4 ri = rS[i0 + ii];               // hoisted: loaded once
        float rx = ri.x, ry = ri.y, rz = ri.z;
        #pragma unroll
        for (int k = 0; k < 8; k++) {
            int jj = jb + k * 32;
            float4 rj = rS[jj];
            float dx = rx - rj.x, dy = ry - rj.y, dz = rz - rj.z;
            float u = fmaf(dx, dx, fmaf(dy, dy, dz * dz));
            int it = (int)(fmaf(u, inv_h, 0.5f));
            it = min(it, TLUT - 1);
            tS[jj * 16 + ii] = (unsigned short)(it << 7);   // byte off = it*128
        }
    }
    __syncthreads();

    // ---- stage 1: warp w owns j in [16w,16w+16); all 16 i; lane = f-pair ----
    const char*  lutLane = smem + (size_t)lane * 4;
    const uint4* tRow    = (const uint4*)(smem + 81920 + (size_t)w * 512);

    __half2 acc[16];
    const __half2 hzero = __float2half2_rn(0.0f);
    #pragma unroll
    for (int ii = 0; ii < 16; ii++) acc[ii] = hzero;

    #pragma unroll
    for (int jj = 0; jj < 16; jj++) {
        const int j = (w << 4) + jj;
        unsigned int fbits = fbS[(j << 5) + lane];
        __half2 fb2 = *reinterpret_cast<__half2*>(&fbits);
        uint4 q0 = tRow[2 * jj], q1 = tRow[2 * jj + 1];     // broadcast: 16 u16 offs
        unsigned int off[16] = {
            q0.x & 0xFFFFu, q0.x >> 16, q0.y & 0xFFFFu, q0.y >> 16,
            q0.z & 0xFFFFu, q0.z >> 16, q0.w & 0xFFFFu, q0.w >> 16,
            q1.x & 0xFFFFu, q1.x >> 16, q1.y & 0xFFFFu, q1.y >> 16,
            q1.z & 0xFFFFu, q1.z >> 16, q1.w & 0xFFFFu, q1.w >> 16};
        #pragma unroll
        for (int ii = 0; ii < 16; ii++) {
            __half2 L = *(const __half2*)(lutLane + off[ii]);
            acc[ii] = __hfma2(L, fb2, acc[ii]);
        }
    }
    __syncthreads();   // all lutS/fbS/tS reads complete

    // ---- write partials over lutS; stage pointwise-MLP weights ----
    #pragma unroll
    for (int ii = 0; ii < 16; ii++)
        partS[((ii << 4) + w) * 32 + lane] = *reinterpret_cast<unsigned int*>(&acc[ii]);
    {
        const float4* w1v = (const float4*)pc_w1;
        float4* w1Sv = (float4*)w1S;
        #pragma unroll
        for (int k = tid; k < FDIM * HDIM / 4; k += THREADS) w1Sv[k] = w1v[k];
        #pragma unroll
        for (int k = tid; k < HDIM * FPRIME; k += THREADS) {
            int hh = k >> 4, p = k & 15;
            w2T[p * 132 + hh] = pc_w2[k];      // transposed for layer-2 float4
        }
        if (tid < HDIM)   b1S[tid] = pc_b1[tid];
        if (tid < FPRIME) b2S[tid] = pc_b2[tid];
    }
    __syncthreads();

    // ---- reduction: warp w = row i; fp32 sum of 16 group partials ----
    {
        float sx = 0.0f, sy = 0.0f;
        #pragma unroll
        for (int g = 0; g < 16; g++) {
            unsigned int pbits = partS[((w << 4) + g) * 32 + lane];
            float2 pv = __half22float2(*reinterpret_cast<__half2*>(&pbits));
            sx += pv.x; sy += pv.y;
        }
        fbarT[(2 * lane) * 18 + w]     = sp(sx);   // transposed [f][i], stride 18
        fbarT[(2 * lane + 1) * 18 + w] = sp(sy);
    }
    __syncthreads();

    // ---- stage 2 layer 1: warps 0..7, rows (2w,2w+1); lane owns 4 h-cols ----
    if (w < 8) {
        float a0[4], a1[4];
        #pragma unroll
        for (int kk = 0; kk < 4; kk++) { a0[kk] = b1S[lane + 32 * kk]; a1[kk] = a0[kk]; }
        #pragma unroll 8
        for (int ff = 0; ff < FDIM; ff++) {
            float2 fv = *(const float2*)(fbarT + ff * 18 + 2 * w);   // broadcast
            #pragma unroll
            for (int kk = 0; kk < 4; kk++) {
                float wv = w1S[ff * HDIM + lane + 32 * kk];
                a0[kk] = fmaf(fv.x, wv, a0[kk]);
                a1[kk] = fmaf(fv.y, wv, a1[kk]);
            }
        }
        #pragma unroll
        for (int kk = 0; kk < 4; kk++) {
            h2S[(2 * w) * 132 + lane + 32 * kk]     = sp(a0[kk]);
            h2S[(2 * w + 1) * 132 + lane + 32 * kk] = sp(a1[kk]);
        }
    }
    __syncthreads();

    // ---- stage 2 layer 2: 256 threads = (row i, out-col p), float4 loads ----
    if (tid < ITILE * FPRIME) {
        int i = tid >> 4, p = tid & 15;
        float o = b2S[p];
        const float4* hv4 = (const float4*)(h2S + i * 132);
        const float4* wv4 = (const float4*)(w2T + p * 132);
        #pragma unroll 8
        for (int hh = 0; hh < HDIM / 4; hh++) {
            float4 hv = hv4[hh], wv = wv4[hh];
            o = fmaf(hv.x, wv.x, o);
            o = fmaf(hv.y, wv.y, o);
            o = fmaf(hv.z, wv.z, o);
            o = fmaf(hv.w, wv.w, o);
        }
        out[((size_t)(b * NPTS + i0 + i)) * FPRIME + p] = sp(o);
    }
}

// ---------------------------------------------------------------------------
extern "C" void kernel_launch(void* const* d_in, const int* in_sizes, int n_in,
                              void* d_out, int out_size) {
    const float* r     = (const float*)d_in[0];
    const float* f     = (const float*)d_in[1];
    const float* mp_w1 = (const float*)d_in[2];
    const float* mp_b1 = (const float*)d_in[3];
    const float* mp_w2 = (const float*)d_in[4];
    const float* mp_b2 = (const float*)d_in[5];
    const float* pc_w1 = (const float*)d_in[6];
    const float* pc_b1 = (const float*)d_in[7];
    const float* pc_w2 = (const float*)d_in[8];
    const float* pc_b2 = (const float*)d_in[9];
    float* out = (float*)d_out;

    build_lut_kernel<<<TLUT, 128>>>(mp_w1, mp_b1, mp_w2, mp_b2);

    cudaFuncSetAttribute(property_predictor_main,
                         cudaFuncAttributeMaxDynamicSharedMemorySize, 94208);
    dim3 grid(NPTS / ITILE, BATCH);
    property_predictor_main<<<grid, THREADS, 94208>>>(
        r, f, pc_w1, pc_b1, pc_w2, pc_b2, out);
}

// round 13
// speedup vs baseline: 1.0024x; 1.0024x over previous
#include <cuda_runtime.h>
#include <cuda_fp16.h>
#include <math.h>

#define BATCH   16
#define NPTS    256
#define FDIM    64
#define FPRIME  16
#define HDIM    128
#define TLUT    384            // knots uniform in u = d^2 over [0, 3]
#define UMAX    3.0f
#define ITILE   16
#define THREADS 512

// nearest-neighbor LUT in u = d^2: row t = 64 halves (128 B), g(sqrt(t*h_u))
__device__ __half g_lutHalf[TLUT * FDIM];

__device__ __forceinline__ float sp(float x) {
    return fmaxf(x, 0.0f) + log1pf(expf(-fabsf(x)));
}

// ---------------------------------------------------------------------------
// LUT build: 384 blocks x 128 threads; dot split into two 64-term half-sums.
// ---------------------------------------------------------------------------
__global__ __launch_bounds__(128)
void build_lut_kernel(const float* __restrict__ mp_w1,
                      const float* __restrict__ mp_b1,
                      const float* __restrict__ mp_w2,
                      const float* __restrict__ mp_b2) {
    __shared__ float hid[HDIM];
    __shared__ float part[2][FDIM];
    const int t = blockIdx.x, tid = threadIdx.x;
    const float u = (float)t * (UMAX / (float)TLUT);
    const float d = sqrtf(u);
    hid[tid] = sp(fmaf(d, mp_w1[tid], mp_b1[tid]));
    __syncthreads();
    {
        int ff = tid & 63, half = tid >> 6;
        float a = 0.0f;
        #pragma unroll 8
        for (int h = 0; h < 64; h++)
            a = fmaf(hid[half * 64 + h], __ldg(mp_w2 + (half * 64 + h) * FDIM + ff), a);
        part[half][ff] = a;
    }
    __syncthreads();
    if (tid < FDIM) {
        float a = mp_b2[tid] + part[0][tid] + part[1][tid];
        g_lutHalf[t * FDIM + tid] = __float2half_rn(sp(a));
    }
}

// ---------------------------------------------------------------------------
// Main fused kernel. CTA = (16-i tile, batch); grid 256; 512 thr; 2 CTAs/SM.
// SMEM (94208 B):
//   [0,    49152)  lutS  LUT rows (384 x 128 B)
//   [49152,81920)  fbS   f tile half2 [j*32 + lane]
//   [81920,90112)  tS    u16 pre-shifted byte-offset (it<<7), layout [j][i]
//   [90112,94208)  rS    float4 positions
// Overlays (after stage-1 sync):
//   partS @0     (16 i * 16 g * 32 lane u32 = 32768)       over lutS
//   fbarT @32768 (64 f * stride 18 f32 = 4608)             over lutS
//   h2S   @37376 (16 * 132 f32 = 8448; ends 45824)         over lutS
//   w1S   @49152 (64*128 f32 = 32768)                      over fbS
//   w2T   @81920 (16 p * stride 132 f32 = 8448)            over tS (+256B rS)
//   b1S   @90624, b2S @91136                               over rS tail
// ---------------------------------------------------------------------------
__global__ __launch_bounds__(THREADS, 2)
void property_predictor_main(const float* __restrict__ r,
                             const float* __restrict__ f,
                             const float* __restrict__ pc_w1,
                             const float* __restrict__ pc_b1,
                             const float* __restrict__ pc_w2,
                             const float* __restrict__ pc_b2,
                             float* __restrict__ out) {
    extern __shared__ char smem[];
    unsigned int*   fbS   = (unsigned int*)(smem + 49152);
    unsigned short* tS    = (unsigned short*)(smem + 81920);
    float4*         rS    = (float4*)(smem + 90112);
    unsigned int*   partS = (unsigned int*)smem;
    float* fbarT = (float*)(smem + 32768);
    float* h2S   = (float*)(smem + 37376);
    float* w1S   = (float*)(smem + 49152);
    float* w2T   = (float*)(smem + 81920);
    float* b1S   = (float*)(smem + 90624);
    float* b2S   = (float*)(smem + 91136);

    const int b    = blockIdx.y;
    const int i0   = blockIdx.x * ITILE;
    const int tid  = threadIdx.x;
    const int w    = tid >> 5;
    const int lane = tid & 31;

    // ---- tile loads (vectorized) ----
    {
        const uint4* lutG = (const uint4*)g_lutHalf;
        uint4* lutSv = (uint4*)smem;
        #pragma unroll
        for (int k = tid; k < TLUT * 8; k += THREADS) lutSv[k] = lutG[k];
    }
    {
        const float4* fbG = (const float4*)(f + (size_t)b * NPTS * FDIM);
        #pragma unroll
        for (int k = tid; k < NPTS * 16; k += THREADS) {
            float4 v = fbG[k];
            __half2 h0 = __floats2half2_rn(v.x, v.y);
            __half2 h1 = __floats2half2_rn(v.z, v.w);
            fbS[2 * k]     = *reinterpret_cast<unsigned int*>(&h0);
            fbS[2 * k + 1] = *reinterpret_cast<unsigned int*>(&h1);
        }
    }
    {
        const float* rG = r + (size_t)b * NPTS * 3;
        if (tid < NPTS)
            rS[tid] = make_float4(rG[3 * tid], rG[3 * tid + 1], rG[3 * tid + 2], 0.0f);
    }
    __syncthreads();

    // ---- stage A: nearest u-knot byte offsets, NO sqrt. tS[j*16 + i] ----
    {
        const float inv_h = (float)TLUT / UMAX;
        const int ii = tid & 15;               // fixed i per thread
        const int jb = tid >> 4;               // j-group: 8 j's, stride 32
        float4 ri = rS[i0 + ii];               // hoisted: loaded once
        float rx = ri.x, ry = ri.y, rz = ri.z;
        #pragma unroll
        for (int k = 0; k < 8; k++) {
            int jj = jb + k * 32;
            float4 rj = rS[jj];
            float dx = rx - rj.x, dy = ry - rj.y, dz = rz - rj.z;
            float u = fmaf(dx, dx, fmaf(dy, dy, dz * dz));
            int it = (int)(fmaf(u, inv_h, 0.5f));
            it = min(it, TLUT - 1);
            tS[jj * 16 + ii] = (unsigned short)(it << 7);   // byte off = it*128
        }
    }
    __syncthreads();

    // ---- stage 1: warp w owns j in [16w,16w+16); all 16 i; lane = f-pair ----
    const char*  lutLane = smem + (size_t)lane * 4;
    const uint4* tRow    = (const uint4*)(smem + 81920 + (size_t)w * 512);

    __half2 acc[16];
    const __half2 hzero = __float2half2_rn(0.0f);
    #pragma unroll
    for (int ii = 0; ii < 16; ii++) acc[ii] = hzero;

    #pragma unroll
    for (int jj = 0; jj < 16; jj++) {
        const int j = (w << 4) + jj;
        unsigned int fbits = fbS[(j << 5) + lane];
        __half2 fb2 = *reinterpret_cast<__half2*>(&fbits);
        uint4 q0 = tRow[2 * jj], q1 = tRow[2 * jj + 1];     // broadcast: 16 u16 offs
        unsigned int off[16] = {
            q0.x & 0xFFFFu, q0.x >> 16, q0.y & 0xFFFFu, q0.y >> 16,
            q0.z & 0xFFFFu, q0.z >> 16, q0.w & 0xFFFFu, q0.w >> 16,
            q1.x & 0xFFFFu, q1.x >> 16, q1.y & 0xFFFFu, q1.y >> 16,
            q1.z & 0xFFFFu, q1.z >> 16, q1.w & 0xFFFFu, q1.w >> 16};
        #pragma unroll
        for (int ii = 0; ii < 16; ii++) {
            __half2 L = *(const __half2*)(lutLane + off[ii]);
            acc[ii] = __hfma2(L, fb2, acc[ii]);
        }
    }
    __syncthreads();   // all lutS/fbS/tS reads complete

    // ---- write partials over lutS; stage pointwise-MLP weights ----
    #pragma unroll
    for (int ii = 0; ii < 16; ii++)
        partS[((ii << 4) + w) * 32 + lane] = *reinterpret_cast<unsigned int*>(&acc[ii]);
    {
        const float4* w1v = (const float4*)pc_w1;
        float4* w1Sv = (float4*)w1S;
        #pragma unroll
        for (int k = tid; k < FDIM * HDIM / 4; k += THREADS) w1Sv[k] = w1v[k];
        #pragma unroll
        for (int k = tid; k < HDIM * FPRIME; k += THREADS) {
            int hh = k >> 4, p = k & 15;
            w2T[p * 132 + hh] = pc_w2[k];      // transposed for layer-2 float4
        }
        if (tid < HDIM)   b1S[tid] = pc_b1[tid];
        if (tid < FPRIME) b2S[tid] = pc_b2[tid];
    }
    __syncthreads();

    // ---- reduction: warp w = row i; fp32 sum of 16 group partials ----
    {
        float sx = 0.0f, sy = 0.0f;
        #pragma unroll
        for (int g = 0; g < 16; g++) {
            unsigned int pbits = partS[((w << 4) + g) * 32 + lane];
            float2 pv = __half22float2(*reinterpret_cast<__half2*>(&pbits));
            sx += pv.x; sy += pv.y;
        }
        fbarT[(2 * lane) * 18 + w]     = sp(sx);   // transposed [f][i], stride 18
        fbarT[(2 * lane + 1) * 18 + w] = sp(sy);
    }
    __syncthreads();

    // ---- stage 2 layer 1: warps 0..7, rows (2w,2w+1); lane owns 4 h-cols ----
    if (w < 8) {
        float a0[4], a1[4];
        #pragma unroll
        for (int kk = 0; kk < 4; kk++) { a0[kk] = b1S[lane + 32 * kk]; a1[kk] = a0[kk]; }
        #pragma unroll 8
        for (int ff = 0; ff < FDIM; ff++) {
            float2 fv = *(const float2*)(fbarT + ff * 18 + 2 * w);   // broadcast
            #pragma unroll
            for (int kk = 0; kk < 4; kk++) {
                float wv = w1S[ff * HDIM + lane + 32 * kk];
                a0[kk] = fmaf(fv.x, wv, a0[kk]);
                a1[kk] = fmaf(fv.y, wv, a1[kk]);
            }
        }
        #pragma unroll
        for (int kk = 0; kk < 4; kk++) {
            h2S[(2 * w) * 132 + lane + 32 * kk]     = sp(a0[kk]);
            h2S[(2 * w + 1) * 132 + lane + 32 * kk] = sp(a1[kk]);
        }
    }
    __syncthreads();

    // ---- stage 2 layer 2: 256 threads = (row i, out-col p), float4 loads ----
    if (tid < ITILE * FPRIME) {
        int i = tid >> 4, p = tid & 15;
        float o = b2S[p];
        const float4* hv4 = (const float4*)(h2S + i * 132);
        const float4* wv4 = (const float4*)(w2T + p * 132);
        #pragma unroll 8
        for (int hh = 0; hh < HDIM / 4; hh++) {
            float4 hv = hv4[hh], wv = wv4[hh];
            o = fmaf(hv.x, wv.x, o);
            o = fmaf(hv.y, wv.y, o);
            o = fmaf(hv.z, wv.z, o);
            o = fmaf(hv.w, wv.w, o);
        }
        out[((size_t)(b * NPTS + i0 + i)) * FPRIME + p] = sp(o);
    }
}

// ---------------------------------------------------------------------------
extern "C" void kernel_launch(void* const* d_in, const int* in_sizes, int n_in,
                              void* d_out, int out_size) {
    const float* r     = (const float*)d_in[0];
    const float* f     = (const float*)d_in[1];
    const float* mp_w1 = (const float*)d_in[2];
    const float* mp_b1 = (const float*)d_in[3];
    const float* mp_w2 = (const float*)d_in[4];
    const float* mp_b2 = (const float*)d_in[5];
    const float* pc_w1 = (const float*)d_in[6];
    const float* pc_b1 = (const float*)d_in[7];
    const float* pc_w2 = (const float*)d_in[8];
    const float* pc_b2 = (const float*)d_in[9];
    float* out = (float*)d_out;

    build_lut_kernel<<<TLUT, 128>>>(mp_w1, mp_b1, mp_w2, mp_b2);

    cudaFuncSetAttribute(property_predictor_main,
                         cudaFuncAttributeMaxDynamicSharedMemorySize, 94208);
    dim3 grid(NPTS / ITILE, BATCH);
    property_predictor_main<<<grid, THREADS, 94208>>>(
        r, f, pc_w1, pc_b1, pc_w2, pc_b2, out);
}

// round 14
// speedup vs baseline: 1.0048x; 1.0024x over previous
#include <cuda_runtime.h>
#include <cuda_fp16.h>
#include <math.h>

#define BATCH   16
#define NPTS    256
#define FDIM    64
#define FPRIME  16
#define HDIM    128
#define TLUT    384            // knots uniform in u = d^2 over [0, 3]
#define UMAX    3.0f
#define ITILE   16
#define THREADS 512

// nearest-neighbor LUT in u = d^2: row t = 64 halves (128 B), g(sqrt(t*h_u))
__device__ __half g_lutHalf[TLUT * FDIM];

__device__ __forceinline__ float sp(float x) {
    return fmaxf(x, 0.0f) + log1pf(expf(-fabsf(x)));
}

// ---------------------------------------------------------------------------
// LUT build: 384 blocks x 128 threads; dot split into two 64-term half-sums.
// ---------------------------------------------------------------------------
__global__ __launch_bounds__(128)
void build_lut_kernel(const float* __restrict__ mp_w1,
                      const float* __restrict__ mp_b1,
                      const float* __restrict__ mp_w2,
                      const float* __restrict__ mp_b2) {
    __shared__ float hid[HDIM];
    __shared__ float part[2][FDIM];
    const int t = blockIdx.x, tid = threadIdx.x;
    const float u = (float)t * (UMAX / (float)TLUT);
    const float d = sqrtf(u);
    hid[tid] = sp(fmaf(d, mp_w1[tid], mp_b1[tid]));
    __syncthreads();
    {
        int ff = tid & 63, half = tid >> 6;
        float a = 0.0f;
        #pragma unroll 8
        for (int h = 0; h < 64; h++)
            a = fmaf(hid[half * 64 + h], __ldg(mp_w2 + (half * 64 + h) * FDIM + ff), a);
        part[half][ff] = a;
    }
    __syncthreads();
    if (tid < FDIM) {
        float a = mp_b2[tid] + part[0][tid] + part[1][tid];
        g_lutHalf[t * FDIM + tid] = __float2half_rn(sp(a));
    }
}

// ---------------------------------------------------------------------------
// Main fused kernel. CTA = (16-i tile, batch); grid 256; 512 thr; 2 CTAs/SM.
// SMEM (94208 B):
//   [0,    49152)  lutS  LUT rows (384 x 128 B)
//   [49152,81920)  fbS   f tile half2 [j*32 + lane]
//   [81920,90112)  tS    u16 pre-shifted byte-offset (it<<7), layout [j][i]
//   [90112,94208)  rS    float4 positions
// Overlays (after stage-1 sync):
//   partS @0     (16 i * 16 g * 32 lane u32 = 32768)       over lutS
//   fbarT @32768 (64 f * stride 18 f32 = 4608)             over lutS
//   h2S   @37376 (16 * 132 f32 = 8448; ends 45824)         over lutS
//   w1S   @49152 (64*128 f32 = 32768)                      over fbS
//   w2T   @81920 (16 p * stride 132 f32 = 8448)            over tS (+256B rS)
//   b1S   @90624, b2S @91136                               over rS tail
// ---------------------------------------------------------------------------
__global__ __launch_bounds__(THREADS, 2)
void property_predictor_main(const float* __restrict__ r,
                             const float* __restrict__ f,
                             const float* __restrict__ pc_w1,
                             const float* __restrict__ pc_b1,
                             const float* __restrict__ pc_w2,
                             const float* __restrict__ pc_b2,
                             float* __restrict__ out) {
    extern __shared__ char smem[];
    unsigned int*   fbS   = (unsigned int*)(smem + 49152);
    unsigned short* tS    = (unsigned short*)(smem + 81920);
    float4*         rS    = (float4*)(smem + 90112);
    unsigned int*   partS = (unsigned int*)smem;
    float* fbarT = (float*)(smem + 32768);
    float* h2S   = (float*)(smem + 37376);
    float* w1S   = (float*)(smem + 49152);
    float* w2T   = (float*)(smem + 81920);
    float* b1S   = (float*)(smem + 90624);
    float* b2S   = (float*)(smem + 91136);

    const int b    = blockIdx.y;
    const int i0   = blockIdx.x * ITILE;
    const int tid  = threadIdx.x;
    const int w    = tid >> 5;
    const int lane = tid & 31;

    // ---- tile loads (vectorized) ----
    {
        const uint4* lutG = (const uint4*)g_lutHalf;
        uint4* lutSv = (uint4*)smem;
        #pragma unroll
        for (int k = tid; k < TLUT * 8; k += THREADS) lutSv[k] = lutG[k];
    }
    {
        const float4* fbG = (const float4*)(f + (size_t)b * NPTS * FDIM);
        #pragma unroll
        for (int k = tid; k < NPTS * 16; k += THREADS) {
            float4 v = fbG[k];
            __half2 h0 = __floats2half2_rn(v.x, v.y);
            __half2 h1 = __floats2half2_rn(v.z, v.w);
            fbS[2 * k]     = *reinterpret_cast<unsigned int*>(&h0);
            fbS[2 * k + 1] = *reinterpret_cast<unsigned int*>(&h1);
        }
    }
    {
        const float* rG = r + (size_t)b * NPTS * 3;
        if (tid < NPTS)
            rS[tid] = make_float4(rG[3 * tid], rG[3 * tid + 1], rG[3 * tid + 2], 0.0f);
    }
    __syncthreads();

    // ---- stage A: nearest u-knot byte offsets, NO sqrt. tS[j*16 + i] ----
    {
        const float inv_h = (float)TLUT / UMAX;
        const int ii = tid & 15;               // fixed i per thread
        const int jb = tid >> 4;               // j-group: 8 j's, stride 32
        float4 ri = rS[i0 + ii];               // hoisted: loaded once
        float rx = ri.x, ry = ri.y, rz = ri.z;
        #pragma unroll
        for (int k = 0; k < 8; k++) {
            int jj = jb + k * 32;
            float4 rj = rS[jj];
            float dx = rx - rj.x, dy = ry - rj.y, dz = rz - rj.z;
            float u = fmaf(dx, dx, fmaf(dy, dy, dz * dz));
            int it = (int)(fmaf(u, inv_h, 0.5f));
            it = min(it, TLUT - 1);
            tS[jj * 16 + ii] = (unsigned short)(it << 7);   // byte off = it*128
        }
    }
    __syncthreads();

    // ---- stage 1: warp w owns j in [16w,16w+16); all 16 i; lane = f-pair ----
    const char*  lutLane = smem + (size_t)lane * 4;
    const uint4* tRow    = (const uint4*)(smem + 81920 + (size_t)w * 512);

    __half2 acc[16];
    const __half2 hzero = __float2half2_rn(0.0f);
    #pragma unroll
    for (int ii = 0; ii < 16; ii++) acc[ii] = hzero;

    #pragma unroll
    for (int jj = 0; jj < 16; jj++) {
        const int j = (w << 4) + jj;
        unsigned int fbits = fbS[(j << 5) + lane];
        __half2 fb2 = *reinterpret_cast<__half2*>(&fbits);
        uint4 q0 = tRow[2 * jj], q1 = tRow[2 * jj + 1];     // broadcast: 16 u16 offs
        unsigned int off[16] = {
            q0.x & 0xFFFFu, q0.x >> 16, q0.y & 0xFFFFu, q0.y >> 16,
            q0.z & 0xFFFFu, q0.z >> 16, q0.w & 0xFFFFu, q0.w >> 16,
            q1.x & 0xFFFFu, q1.x >> 16, q1.y & 0xFFFFu, q1.y >> 16,
            q1.z & 0xFFFFu, q1.z >> 16, q1.w & 0xFFFFu, q1.w >> 16};
        #pragma unroll
        for (int ii = 0; ii < 16; ii++) {
            __half2 L = *(const __half2*)(lutLane + off[ii]);
            acc[ii] = __hfma2(L, fb2, acc[ii]);
        }
    }
    __syncthreads();   // all lutS/fbS/tS reads complete

    // ---- write partials over lutS; stage pointwise-MLP weights ----
    #pragma unroll
    for (int ii = 0; ii < 16; ii++)
        partS[((ii << 4) + w) * 32 + lane] = *reinterpret_cast<unsigned int*>(&acc[ii]);
    {
        const float4* w1v = (const float4*)pc_w1;
        float4* w1Sv = (float4*)w1S;
        #pragma unroll
        for (int k = tid; k < FDIM * HDIM / 4; k += THREADS) w1Sv[k] = w1v[k];
        #pragma unroll
        for (int k = tid; k < HDIM * FPRIME; k += THREADS) {
            int hh = k >> 4, p = k & 15;
            w2T[p * 132 + hh] = pc_w2[k];      // transposed for layer-2 float4
        }
        if (tid < HDIM)   b1S[tid] = pc_b1[tid];
        if (tid < FPRIME) b2S[tid] = pc_b2[tid];
    }
    __syncthreads();

    // ---- reduction: warp w = row i; fp32 sum of 16 group partials ----
    {
        float sx = 0.0f, sy = 0.0f;
        #pragma unroll
        for (int g = 0; g < 16; g++) {
            unsigned int pbits = partS[((w << 4) + g) * 32 + lane];
            float2 pv = __half22float2(*reinterpret_cast<__half2*>(&pbits));
            sx += pv.x; sy += pv.y;
        }
        fbarT[(2 * lane) * 18 + w]     = sp(sx);   // transposed [f][i], stride 18
        fbarT[(2 * lane + 1) * 18 + w] = sp(sy);
    }
    __syncthreads();

    // ---- stage 2 layer 1: warps 0..7, rows (2w,2w+1); lane owns 4 h-cols ----
    if (w < 8) {
        float a0[4], a1[4];
        #pragma unroll
        for (int kk = 0; kk < 4; kk++) { a0[kk] = b1S[lane + 32 * kk]; a1[kk] = a0[kk]; }
        #pragma unroll 8
        for (int ff = 0; ff < FDIM; ff++) {
            float2 fv = *(const float2*)(fbarT + ff * 18 + 2 * w);   // broadcast
            #pragma unroll
            for (int kk = 0; kk < 4; kk++) {
                float wv = w1S[ff * HDIM + lane + 32 * kk];
                a0[kk] = fmaf(fv.x, wv, a0[kk]);
                a1[kk] = fmaf(fv.y, wv, a1[kk]);
            }
        }
        #pragma unroll
        for (int kk = 0; kk < 4; kk++) {
            h2S[(2 * w) * 132 + lane + 32 * kk]     = sp(a0[kk]);
            h2S[(2 * w + 1) * 132 + lane + 32 * kk] = sp(a1[kk]);
        }
    }
    __syncthreads();

    // ---- stage 2 layer 2: 256 threads = (row i, out-col p), float4 loads ----
    if (tid < ITILE * FPRIME) {
        int i = tid >> 4, p = tid & 15;
        float o = b2S[p];
        const float4* hv4 = (const float4*)(h2S + i * 132);
        const float4* wv4 = (const float4*)(w2T + p * 132);
        #pragma unroll 8
        for (int hh = 0; hh < HDIM / 4; hh++) {
            float4 hv = hv4[hh], wv = wv4[hh];
            o = fmaf(hv.x, wv.x, o);
            o = fmaf(hv.y, wv.y, o);
            o = fmaf(hv.z, wv.z, o);
            o = fmaf(hv.w, wv.w, o);
        }
        out[((size_t)(b * NPTS + i0 + i)) * FPRIME + p] = sp(o);
    }
}

// ---------------------------------------------------------------------------
extern "C" void kernel_launch(void* const* d_in, const int* in_sizes, int n_in,
                              void* d_out, int out_size) {
    const float* r     = (const float*)d_in[0];
    const float* f     = (const float*)d_in[1];
    const float* mp_w1 = (const float*)d_in[2];
    const float* mp_b1 = (const float*)d_in[3];
    const float* mp_w2 = (const float*)d_in[4];
    const float* mp_b2 = (const float*)d_in[5];
    const float* pc_w1 = (const float*)d_in[6];
    const float* pc_b1 = (const float*)d_in[7];
    const float* pc_w2 = (const float*)d_in[8];
    const float* pc_b2 = (const float*)d_in[9];
    float* out = (float*)d_out;

    build_lut_kernel<<<TLUT, 128>>>(mp_w1, mp_b1, mp_w2, mp_b2);

    cudaFuncSetAttribute(property_predictor_main,
                         cudaFuncAttributeMaxDynamicSharedMemorySize, 94208);
    dim3 grid(NPTS / ITILE, BATCH);
    property_predictor_main<<<grid, THREADS, 94208>>>(
        r, f, pc_w1, pc_b1, pc_w2, pc_b2, out);
}

// round 15
// speedup vs baseline: 1.0651x; 1.0599x over previous
#include <cuda_runtime.h>
#include <cuda_fp16.h>
#include <math.h>

#define BATCH   16
#define NPTS    256
#define FDIM    64
#define FPRIME  16
#define HDIM    128
#define TLUT    384            // knots uniform in u = d^2 over [0, 3]
#define UMAX    3.0f
#define ITILE   16
#define THREADS 512

// nearest-neighbor LUT in u = d^2: row t = 64 halves (128 B), g(sqrt(t*h_u))
__device__ __half g_lutHalf[TLUT * FDIM];

__device__ __forceinline__ float sp(float x) {
    return fmaxf(x, 0.0f) + log1pf(expf(-fabsf(x)));
}

// ---------------------------------------------------------------------------
// LUT build: 384 blocks x 128 threads; dot split into two 64-term half-sums.
// ---------------------------------------------------------------------------
__global__ __launch_bounds__(128)
void build_lut_kernel(const float* __restrict__ mp_w1,
                      const float* __restrict__ mp_b1,
                      const float* __restrict__ mp_w2,
                      const float* __restrict__ mp_b2) {
    __shared__ float hid[HDIM];
    __shared__ float part[2][FDIM];
    const int t = blockIdx.x, tid = threadIdx.x;
    const float u = (float)t * (UMAX / (float)TLUT);
    const float d = sqrtf(u);
    hid[tid] = sp(fmaf(d, mp_w1[tid], mp_b1[tid]));
    __syncthreads();
    {
        int ff = tid & 63, half = tid >> 6;
        float a = 0.0f;
        #pragma unroll 8
        for (int h = 0; h < 64; h++)
            a = fmaf(hid[half * 64 + h], __ldg(mp_w2 + (half * 64 + h) * FDIM + ff), a);
        part[half][ff] = a;
    }
    __syncthreads();
    if (tid < FDIM) {
        float a = mp_b2[tid] + part[0][tid] + part[1][tid];
        g_lutHalf[t * FDIM + tid] = __float2half_rn(sp(a));
    }
}

// ---------------------------------------------------------------------------
// Main fused kernel. CTA = (16-i tile, batch); grid 256; 512 thr; 2 CTAs/SM.
// SMEM (94208 B):
//   [0,    49152)  lutS  LUT rows (384 x 128 B)
//   [49152,81920)  fbS   f tile half2 [j*32 + lane]
//   [81920,90112)  tS    u16 pre-shifted byte-offset (it<<7), layout [j][i]
//   [90112,94208)  rS    float4 positions
// Overlays (after stage-1 sync):
//   partS @0     (16 i * 16 g * 32 lane u32 = 32768)       over lutS
//   fbarT @32768 (64 f * stride 18 f32 = 4608)             over lutS
//   h2S   @37376 (16 * 132 f32 = 8448; ends 45824)         over lutS
//   w1S   @49152 (64*128 f32 = 32768)                      over fbS
//   w2T   @81920 (16 p * stride 132 f32 = 8448)            over tS (+256B rS)
//   b1S   @90624, b2S @91136                               over rS tail
// ---------------------------------------------------------------------------
__global__ __launch_bounds__(THREADS, 2)
void property_predictor_main(const float* __restrict__ r,
                             const float* __restrict__ f,
                             const float* __restrict__ pc_w1,
                             const float* __restrict__ pc_b1,
                             const float* __restrict__ pc_w2,
                             const float* __restrict__ pc_b2,
                             float* __restrict__ out) {
    extern __shared__ char smem[];
    unsigned int*   fbS   = (unsigned int*)(smem + 49152);
    unsigned short* tS    = (unsigned short*)(smem + 81920);
    float4*         rS    = (float4*)(smem + 90112);
    unsigned int*   partS = (unsigned int*)smem;
    float* fbarT = (float*)(smem + 32768);
    float* h2S   = (float*)(smem + 37376);
    float* w1S   = (float*)(smem + 49152);
    float* w2T   = (float*)(smem + 81920);
    float* b1S   = (float*)(smem + 90624);
    float* b2S   = (float*)(smem + 91136);

    const int b    = blockIdx.y;
    const int i0   = blockIdx.x * ITILE;
    const int tid  = threadIdx.x;
    const int w    = tid >> 5;
    const int lane = tid & 31;

    // ---- tile loads (vectorized) ----
    {
        const uint4* lutG = (const uint4*)g_lutHalf;
        uint4* lutSv = (uint4*)smem;
        #pragma unroll
        for (int k = tid; k < TLUT * 8; k += THREADS) lutSv[k] = lutG[k];
    }
    {
        const float4* fbG = (const float4*)(f + (size_t)b * NPTS * FDIM);
        #pragma unroll
        for (int k = tid; k < NPTS * 16; k += THREADS) {
            float4 v = fbG[k];
            __half2 h0 = __floats2half2_rn(v.x, v.y);
            __half2 h1 = __floats2half2_rn(v.z, v.w);
            fbS[2 * k]     = *reinterpret_cast<unsigned int*>(&h0);
            fbS[2 * k + 1] = *reinterpret_cast<unsigned int*>(&h1);
        }
    }
    {
        const float* rG = r + (size_t)b * NPTS * 3;
        if (tid < NPTS)
            rS[tid] = make_float4(rG[3 * tid], rG[3 * tid + 1], rG[3 * tid + 2], 0.0f);
    }
    __syncthreads();

    // ---- stage A: nearest u-knot byte offsets, NO sqrt. tS[j*16 + i] ----
    {
        const float inv_h = (float)TLUT / UMAX;
        const int ii = tid & 15;               // fixed i per thread
        const int jb = tid >> 4;               // j-group: 8 j's, stride 32
        float4 ri = rS[i0 + ii];               // hoisted: loaded once
        float rx = ri.x, ry = ri.y, rz = ri.z;
        #pragma unroll
        for (int k = 0; k < 8; k++) {
            int jj = jb + k * 32;
            float4 rj = rS[jj];
            float dx = rx - rj.x, dy = ry - rj.y, dz = rz - rj.z;
            float u = fmaf(dx, dx, fmaf(dy, dy, dz * dz));
            int it = (int)(fmaf(u, inv_h, 0.5f));
            it = min(it, TLUT - 1);
            tS[jj * 16 + ii] = (unsigned short)(it << 7);   // byte off = it*128
        }
    }
    __syncthreads();

    // ---- stage 1: warp w owns j in [16w,16w+16); all 16 i; lane = f-pair ----
    const char*  lutLane = smem + (size_t)lane * 4;
    const uint4* tRow    = (const uint4*)(smem + 81920 + (size_t)w * 512);

    __half2 acc[16];
    const __half2 hzero = __float2half2_rn(0.0f);
    #pragma unroll
    for (int ii = 0; ii < 16; ii++) acc[ii] = hzero;

    #pragma unroll
    for (int jj = 0; jj < 16; jj++) {
        const int j = (w << 4) + jj;
        unsigned int fbits = fbS[(j << 5) + lane];
        __half2 fb2 = *reinterpret_cast<__half2*>(&fbits);
        uint4 q0 = tRow[2 * jj], q1 = tRow[2 * jj + 1];     // broadcast: 16 u16 offs
        unsigned int off[16] = {
            q0.x & 0xFFFFu, q0.x >> 16, q0.y & 0xFFFFu, q0.y >> 16,
            q0.z & 0xFFFFu, q0.z >> 16, q0.w & 0xFFFFu, q0.w >> 16,
            q1.x & 0xFFFFu, q1.x >> 16, q1.y & 0xFFFFu, q1.y >> 16,
            q1.z & 0xFFFFu, q1.z >> 16, q1.w & 0xFFFFu, q1.w >> 16};
        #pragma unroll
        for (int ii = 0; ii < 16; ii++) {
            __half2 L = *(const __half2*)(lutLane + off[ii]);
            acc[ii] = __hfma2(L, fb2, acc[ii]);
        }
    }
    __syncthreads();   // all lutS/fbS/tS reads complete

    // ---- write partials over lutS; stage pointwise-MLP weights ----
    #pragma unroll
    for (int ii = 0; ii < 16; ii++)
        partS[((ii << 4) + w) * 32 + lane] = *reinterpret_cast<unsigned int*>(&acc[ii]);
    {
        const float4* w1v = (const float4*)pc_w1;
        float4* w1Sv = (float4*)w1S;
        #pragma unroll
        for (int k = tid; k < FDIM * HDIM / 4; k += THREADS) w1Sv[k] = w1v[k];
        #pragma unroll
        for (int k = tid; k < HDIM * FPRIME; k += THREADS) {
            int hh = k >> 4, p = k & 15;
            w2T[p * 132 + hh] = pc_w2[k];      // transposed for layer-2 float4
        }
        if (tid < HDIM)   b1S[tid] = pc_b1[tid];
        if (tid < FPRIME) b2S[tid] = pc_b2[tid];
    }
    __syncthreads();

    // ---- reduction: warp w = row i; fp32 sum of 16 group partials ----
    {
        float sx = 0.0f, sy = 0.0f;
        #pragma unroll
        for (int g = 0; g < 16; g++) {
            unsigned int pbits = partS[((w << 4) + g) * 32 + lane];
            float2 pv = __half22float2(*reinterpret_cast<__half2*>(&pbits));
            sx += pv.x; sy += pv.y;
        }
        fbarT[(2 * lane) * 18 + w]     = sp(sx);   // transposed [f][i], stride 18
        fbarT[(2 * lane + 1) * 18 + w] = sp(sy);
    }
    __syncthreads();

    // ---- stage 2 layer 1: warps 0..7, rows (2w,2w+1); lane owns 4 h-cols ----
    if (w < 8) {
        float a0[4], a1[4];
        #pragma unroll
        for (int kk = 0; kk < 4; kk++) { a0[kk] = b1S[lane + 32 * kk]; a1[kk] = a0[kk]; }
        #pragma unroll 8
        for (int ff = 0; ff < FDIM; ff++) {
            float2 fv = *(const float2*)(fbarT + ff * 18 + 2 * w);   // broadcast
            #pragma unroll
            for (int kk = 0; kk < 4; kk++) {
                float wv = w1S[ff * HDIM + lane + 32 * kk];
                a0[kk] = fmaf(fv.x, wv, a0[kk]);
                a1[kk] = fmaf(fv.y, wv, a1[kk]);
            }
        }
        #pragma unroll
        for (int kk = 0; kk < 4; kk++) {
            h2S[(2 * w) * 132 + lane + 32 * kk]     = sp(a0[kk]);
            h2S[(2 * w + 1) * 132 + lane + 32 * kk] = sp(a1[kk]);
        }
    }
    __syncthreads();

    // ---- stage 2 layer 2: 256 threads = (row i, out-col p), float4 loads ----
    if (tid < ITILE * FPRIME) {
        int i = tid >> 4, p = tid & 15;
        float o = b2S[p];
        const float4* hv4 = (const float4*)(h2S + i * 132);
        const float4* wv4 = (const float4*)(w2T + p * 132);
        #pragma unroll 8
        for (int hh = 0; hh < HDIM / 4; hh++) {
            float4 hv = hv4[hh], wv = wv4[hh];
            o = fmaf(hv.x, wv.x, o);
            o = fmaf(hv.y, wv.y, o);
            o = fmaf(hv.z, wv.z, o);
            o = fmaf(hv.w, wv.w, o);
        }
        out[((size_t)(b * NPTS + i0 + i)) * FPRIME + p] = sp(o);
    }
}

// ---------------------------------------------------------------------------
extern "C" void kernel_launch(void* const* d_in, const int* in_sizes, int n_in,
                              void* d_out, int out_size) {
    const float* r     = (const float*)d_in[0];
    const float* f     = (const float*)d_in[1];
    const float* mp_w1 = (const float*)d_in[2];
    const float* mp_b1 = (const float*)d_in[3];
    const float* mp_w2 = (const float*)d_in[4];
    const float* mp_b2 = (const float*)d_in[5];
    const float* pc_w1 = (const float*)d_in[6];
    const float* pc_b1 = (const float*)d_in[7];
    const float* pc_w2 = (const float*)d_in[8];
    const float* pc_b2 = (const float*)d_in[9];
    float* out = (float*)d_out;

    build_lut_kernel<<<TLUT, 128>>>(mp_w1, mp_b1, mp_w2, mp_b2);

    cudaFuncSetAttribute(property_predictor_main,
                         cudaFuncAttributeMaxDynamicSharedMemorySize, 94208);
    dim3 grid(NPTS / ITILE, BATCH);
    property_predictor_main<<<grid, THREADS, 94208>>>(
        r, f, pc_w1, pc_b1, pc_w2, pc_b2, out);
}